// round 11
// baseline (speedup 1.0000x reference)
#include <cuda_runtime.h>
#include <cuda_fp16.h>
#include <cstdint>

// Problem dims
#define NB   512
#define TQ   128
#define CD   384
#define HD   64
#define MTOT (NB*TQ)
#define SCALE 0.4082482904638631f   // 6^-0.5

// W pre-split: fp16 hi/lo pair words, [n=192][kpair=192]
__device__ __align__(16) uint32_t g_whi[192*192];
__device__ __align__(16) uint32_t g_wlo[192*192];
// Q/K/V as fp16 hi/lo pair words, [row][32]  (Q carries SCALE)
__device__ __align__(16) uint32_t g_qh[MTOT*32];
__device__ __align__(16) uint32_t g_ql[MTOT*32];
__device__ __align__(16) uint32_t g_kh[MTOT*32];
__device__ __align__(16) uint32_t g_kl[MTOT*32];
__device__ __align__(16) uint32_t g_vh[MTOT*32];
__device__ __align__(16) uint32_t g_vl[MTOT*32];

// ---------------- helpers ----------------
__device__ __forceinline__ void mma_f16(float* d, const uint32_t* a,
                                        uint32_t b0, uint32_t b1)
{
    asm("mma.sync.aligned.m16n8k16.row.col.f32.f16.f16.f32 "
        "{%0,%1,%2,%3}, {%4,%5,%6,%7}, {%8,%9}, {%0,%1,%2,%3};"
        : "+f"(d[0]), "+f"(d[1]), "+f"(d[2]), "+f"(d[3])
        : "r"(a[0]), "r"(a[1]), "r"(a[2]), "r"(a[3]), "r"(b0), "r"(b1));
}
#define LDM4(r, a) \
    asm volatile("ldmatrix.sync.aligned.m8n8.x4.shared.b16 {%0,%1,%2,%3}, [%4];" \
        : "=r"((r)[0]), "=r"((r)[1]), "=r"((r)[2]), "=r"((r)[3]) : "r"(a))
#define LDM4T(r, a) \
    asm volatile("ldmatrix.sync.aligned.m8n8.x4.trans.shared.b16 {%0,%1,%2,%3}, [%4];" \
        : "=r"((r)[0]), "=r"((r)[1]), "=r"((r)[2]), "=r"((r)[3]) : "r"(a))

__device__ __forceinline__ void splith(float e0, float e1,
                                       uint32_t& h, uint32_t& l)
{
    __half2 H = __floats2half2_rn(e0, e1);
    float f0 = __low2float(H), f1 = __high2float(H);
    __half2 L = __floats2half2_rn(e0 - f0, e1 - f1);
    h = *(uint32_t*)&H;
    l = *(uint32_t*)&L;
}
__device__ __forceinline__ void cp16(uint32_t s, const void* g) {
    asm volatile("cp.async.cg.shared.global [%0], [%1], 16;" :: "r"(s), "l"(g));
}

// ============================================================================
// Kernel 0: split W -> fp16 hi/lo pair words, [n=192][kpair=192]
// ============================================================================
__global__ __launch_bounds__(256) void wsplit_kernel(
    const float* __restrict__ Wq, const float* __restrict__ Wk,
    const float* __restrict__ Wv)
{
    int idx = blockIdx.x * 256 + threadIdx.x;
    if (idx >= 192 * 192) return;
    int kp = idx / 192, n = idx % 192;        // n fastest -> coalesced reads
    const float* W = (n < 64) ? Wq : (n < 128) ? Wk : Wv;
    int c = n & 63;
    float e0 = W[(size_t)(2 * kp) * HD + c];
    float e1 = W[(size_t)(2 * kp + 1) * HD + c];
    uint32_t h, l;
    splith(e0, e1, h, l);
    g_whi[n * 192 + kp] = h;
    g_wlo[n * 192 + kp] = l;
}

// ============================================================================
// Kernel 1: QKV projection. BM=64, 256 threads / 8 warps, 2 CTAs/SM.
// C[64,192] = x_tile @ [Wq|Wk|Wv], fp16 3-term, BK=32, double-buffered.
// Warp grid 2(M)x4(N), warp tile 32x48.
// ============================================================================
// smem word offsets
#define PA_H  0          // [2][64*20]
#define PA_L  2560
#define PB_H  5120       // [2][192*20]
#define PB_L  12800
#define PJ_SMEM (20480 * 4)   // 81,920 B -> 2 CTAs/SM

__global__ __launch_bounds__(256, 2) void proj_kernel(const float* __restrict__ x)
{
    extern __shared__ uint32_t sw[];
    const uint32_t sb = (uint32_t)__cvta_generic_to_shared(sw);
    const int tid = threadIdx.x;
    const int lane = tid & 31, wid = tid >> 5;
    const int gr = lane >> 2, tg = lane & 3;
    const int mBase = blockIdx.x * 64;

    const int arow = tid >> 2;             // 0..63
    const int kw   = (tid & 3) * 4;
    const float* ag = x + ((size_t)mBase + arow) * CD + (tid & 3) * 8;

    // B loader: 1536 16B-chunks, 6 per thread
    const uint32_t* bl_src[6];
    uint32_t bl_dstw[6];
    #pragma unroll
    for (int j = 0; j < 6; j++) {
        int id = tid + j * 256;
        int hi = (id < 768);
        int i = hi ? id : id - 768;
        int bn = i >> 2, bch = i & 3;
        bl_src[j] = (hi ? g_whi : g_wlo) + bn * 192 + bch * 4;
        bl_dstw[j] = (hi ? PB_H : PB_L) + bn * 20 + bch * 4;
    }
#define PLOADB(buf, t) do {                                                    \
    _Pragma("unroll")                                                          \
    for (int _j = 0; _j < 6; _j++)                                             \
        cp16(sb + (bl_dstw[_j] + (buf) * 3840) * 4, bl_src[_j] + (t) * 16);    \
    asm volatile("cp.async.commit_group;" ::: "memory");                       \
} while (0)

#define STOREA(buf, r0v, r1v) do {                                             \
    uint32_t _h0,_l0,_h1,_l1,_h2,_l2,_h3,_l3;                                  \
    splith((r0v).x, (r0v).y, _h0, _l0); splith((r0v).z, (r0v).w, _h1, _l1);    \
    splith((r1v).x, (r1v).y, _h2, _l2); splith((r1v).z, (r1v).w, _h3, _l3);    \
    uint32_t* _pH = sw + PA_H + (buf) * 1280 + arow * 20 + kw;                 \
    uint32_t* _pL = sw + PA_L + (buf) * 1280 + arow * 20 + kw;                 \
    *(uint2*)_pH = make_uint2(_h0, _h1); *(uint2*)(_pH + 2) = make_uint2(_h2, _h3); \
    *(uint2*)_pL = make_uint2(_l0, _l1); *(uint2*)(_pL + 2) = make_uint2(_l2, _l3); \
} while (0)

    const int wm = (wid & 1) * 32;
    const int wn = (wid >> 1) * 48;

    const int a_r = (lane & 7) + ((lane >> 3) & 1) * 8;
    const int a_c = ((lane >> 4) & 1) * 4;
    const uint32_t aoff0 = ((wm + a_r) * 20 + a_c) * 4;
    const uint32_t aoff1 = ((wm + 16 + a_r) * 20 + a_c) * 4;
    const int b_r = lane & 7;
    const int b_half = (lane >> 3) & 1;
    const int b_nt = (lane >> 4) & 1;
    uint32_t boff[3];
    #pragma unroll
    for (int p = 0; p < 3; p++)
        boff[p] = ((wn + (2 * p + b_nt) * 8 + b_r) * 20 + b_half * 4) * 4;

    float acc[2][6][4];
    #pragma unroll
    for (int mt = 0; mt < 2; mt++)
        #pragma unroll
        for (int nt = 0; nt < 6; nt++)
            #pragma unroll
            for (int i = 0; i < 4; i++) acc[mt][nt][i] = 0.f;

    float4 ar0 = *(const float4*)ag;
    float4 ar1 = *(const float4*)(ag + 4);
    STOREA(0, ar0, ar1);
    PLOADB(0, 0);
    ar0 = *(const float4*)(ag + 32);
    ar1 = *(const float4*)(ag + 36);

    #pragma unroll 2
    for (int t = 0; t < 12; t++) {
        const int buf = t & 1;
        asm volatile("cp.async.wait_group 0;" ::: "memory");
        __syncthreads();
        if (t < 11) {
            STOREA(buf ^ 1, ar0, ar1);
            PLOADB(buf ^ 1, t + 1);
            if (t < 10) {
                ar0 = *(const float4*)(ag + (t + 2) * 32);
                ar1 = *(const float4*)(ag + (t + 2) * 32 + 4);
            }
        }
        const uint32_t aBH = sb + (PA_H + buf * 1280) * 4;
        const uint32_t aBL = sb + (PA_L + buf * 1280) * 4;
        const uint32_t bBH = sb + (PB_H + buf * 3840) * 4;
        const uint32_t bBL = sb + (PB_L + buf * 3840) * 4;
        #pragma unroll
        for (int kk = 0; kk < 2; kk++) {
            uint32_t AH0[4], AH1[4], AL0[4], AL1[4];
            LDM4(AH0, aBH + aoff0 + kk * 32);
            LDM4(AH1, aBH + aoff1 + kk * 32);
            LDM4(AL0, aBL + aoff0 + kk * 32);
            LDM4(AL1, aBL + aoff1 + kk * 32);
            #pragma unroll
            for (int p = 0; p < 3; p++) {
                uint32_t BH[4], BL[4];
                LDM4(BH, bBH + boff[p] + kk * 32);
                LDM4(BL, bBL + boff[p] + kk * 32);
                mma_f16(acc[0][2*p],   AH0, BH[0], BH[1]);
                mma_f16(acc[1][2*p],   AH1, BH[0], BH[1]);
                mma_f16(acc[0][2*p+1], AH0, BH[2], BH[3]);
                mma_f16(acc[1][2*p+1], AH1, BH[2], BH[3]);
                mma_f16(acc[0][2*p],   AH0, BL[0], BL[1]);
                mma_f16(acc[1][2*p],   AH1, BL[0], BL[1]);
                mma_f16(acc[0][2*p+1], AH0, BL[2], BL[3]);
                mma_f16(acc[1][2*p+1], AH1, BL[2], BL[3]);
                mma_f16(acc[0][2*p],   AL0, BH[0], BH[1]);
                mma_f16(acc[1][2*p],   AL1, BH[0], BH[1]);
                mma_f16(acc[0][2*p+1], AL0, BH[2], BH[3]);
                mma_f16(acc[1][2*p+1], AL1, BH[2], BH[3]);
            }
        }
    }

    // ---- epilogue: write Q (xSCALE) / K / V as fp16 hi/lo pair words ----
    #pragma unroll
    for (int nt = 0; nt < 6; nt++) {
        int n = wn + nt * 8;
        uint32_t* Oh = (n < 64) ? g_qh : (n < 128) ? g_kh : g_vh;
        uint32_t* Ol = (n < 64) ? g_ql : (n < 128) ? g_kl : g_vl;
        float sc = (n < 64) ? SCALE : 1.0f;
        int pidx = ((n & 63) >> 1) + tg;
        #pragma unroll
        for (int mt = 0; mt < 2; mt++) {
            int r = mBase + wm + mt * 16 + gr;
            uint32_t h, l;
            splith(acc[mt][nt][0] * sc, acc[mt][nt][1] * sc, h, l);
            Oh[(size_t)r * 32 + pidx] = h;
            Ol[(size_t)r * 32 + pidx] = l;
            splith(acc[mt][nt][2] * sc, acc[mt][nt][3] * sc, h, l);
            Oh[(size_t)(r + 8) * 32 + pidx] = h;
            Ol[(size_t)(r + 8) * 32 + pidx] = l;
        }
    }
}

// ============================================================================
// Kernel 2: attention. 256 threads / 8 warps, 2 CTAs/SM.
// One warp per t-tile (SMSP-balanced map), single-pass online softmax over
// causal s-chunks (2 s-tiles = one k16 unit). No CTA-wide barriers after load.
// smem: 6 tiles [128][36] words = 110,592 B.
// ============================================================================
#define TQH 0
#define TQL 4608
#define TKH 9216
#define TKL 13824
#define TVH 18432
#define TVL 23040
#define AT_SMEM (27648 * 4)   // 110,592 B -> 2 CTAs/SM

__global__ __launch_bounds__(256, 2) void attn_kernel(float* __restrict__ out)
{
    extern __shared__ uint32_t sw[];
    const uint32_t sb = (uint32_t)__cvta_generic_to_shared(sw);
    const int tid = threadIdx.x, b = blockIdx.x;
    const int lane = tid & 31, wid = tid >> 5;
    const int gr = lane >> 2, tg = lane & 3;

    // ---- load 6 tiles via cp.async (row stride 36 words) ----
    {
        const uint32_t* srcs[6] = {g_qh, g_ql, g_kh, g_kl, g_vh, g_vl};
        const int dsts[6] = {TQH, TQL, TKH, TKL, TVH, TVL};
        #pragma unroll
        for (int arr = 0; arr < 6; arr++) {
            const uint32_t* gsrc = srcs[arr] + (size_t)b * 4096;
            #pragma unroll
            for (int i = 0; i < 4; i++) {
                int c = tid + i * 256;          // 0..1023
                int row = c >> 3, off = (c & 7) * 4;
                cp16(sb + (dsts[arr] + row * 36 + off) * 4, gsrc + row * 32 + off);
            }
        }
    }
    asm volatile("cp.async.commit_group;" ::: "memory");
    asm volatile("cp.async.wait_group 0;" ::: "memory");
    __syncthreads();

    // SMSP-balanced t-tile map: warps (s, s+4) -> tiles (s, 7-s)
    const int tt = (wid < 4) ? wid : 11 - wid;
    const int t0 = 16 * tt;
    const int r0 = t0 + gr, r1 = r0 + 8;

    // ldmatrix lane addresses
    const int a_r = (lane & 7) + ((lane >> 3) & 1) * 8;
    const int a_c = ((lane >> 4) & 1) * 4;
    const int g = lane >> 3;
    const uint32_t q_byte = ((t0 + a_r) * 36 + a_c) * 4;
    // K: g0/g1 -> s-tile st0 words 0/4; g2/g3 -> s-tile st1
    const uint32_t k_lane = ((8 * (g >> 1) + (lane & 7)) * 36 + 4 * (g & 1)) * 4;
    // V (trans): g0/g1 -> k rows +0/+8 (word 0); g2/g3 -> +0/+8 (word 4)
    const uint32_t v_lane = ((8 * (g & 1) + (lane & 7)) * 36 + 4 * (g >> 1)) * 4;

    // Q fragments once (SCALE pre-folded)
    uint32_t AH[4][4], AL[4][4];
    #pragma unroll
    for (int kk = 0; kk < 4; kk++) {
        LDM4(AH[kk], sb + TQH * 4 + q_byte + kk * 32);
        LDM4(AL[kk], sb + TQL * 4 + q_byte + kk * 32);
    }

    const float NEG = __int_as_float(0xff800000);
    float m0 = NEG, m1 = NEG, sum0 = 0.f, sum1 = 0.f;
    float oacc[8][4];
    #pragma unroll
    for (int ht = 0; ht < 8; ht++)
        #pragma unroll
        for (int i = 0; i < 4; i++) oacc[ht][i] = 0.f;

    for (int jj = 0; jj <= tt; jj++) {
        // ---- QK for chunk (s rows 16jj..16jj+15) ----
        float s2[2][4];
        #pragma unroll
        for (int q = 0; q < 2; q++)
            #pragma unroll
            for (int i = 0; i < 4; i++) s2[q][i] = 0.f;
        #pragma unroll
        for (int kk = 0; kk < 4; kk++) {
            uint32_t KH[4], KL[4];
            LDM4(KH, sb + TKH * 4 + k_lane + jj * 2304 + kk * 32);
            LDM4(KL, sb + TKL * 4 + k_lane + jj * 2304 + kk * 32);
            mma_f16(s2[0], AH[kk], KH[0], KH[1]);
            mma_f16(s2[1], AH[kk], KH[2], KH[3]);
            mma_f16(s2[0], AH[kk], KL[0], KL[1]);
            mma_f16(s2[1], AH[kk], KL[2], KL[3]);
            mma_f16(s2[0], AL[kk], KH[0], KH[1]);
            mma_f16(s2[1], AL[kk], KH[2], KH[3]);
        }
        // ---- causal mask (only last chunk needs it) ----
        if (jj == tt) {
            int c0 = 16 * jj + 2 * tg;     // tile st0 cols c0, c0+1
            int c1 = c0 + 8;               // tile st1
            if (c0     > r0) s2[0][0] = NEG;
            if (c0 + 1 > r0) s2[0][1] = NEG;
            if (c0     > r1) s2[0][2] = NEG;
            if (c0 + 1 > r1) s2[0][3] = NEG;
            if (c1     > r0) s2[1][0] = NEG;
            if (c1 + 1 > r0) s2[1][1] = NEG;
            if (c1     > r1) s2[1][2] = NEG;
            if (c1 + 1 > r1) s2[1][3] = NEG;
        }
        // ---- online softmax update ----
        float cm0 = fmaxf(fmaxf(s2[0][0], s2[0][1]), fmaxf(s2[1][0], s2[1][1]));
        float cm1 = fmaxf(fmaxf(s2[0][2], s2[0][3]), fmaxf(s2[1][2], s2[1][3]));
        cm0 = fmaxf(cm0, __shfl_xor_sync(0xffffffffu, cm0, 1));
        cm0 = fmaxf(cm0, __shfl_xor_sync(0xffffffffu, cm0, 2));
        cm1 = fmaxf(cm1, __shfl_xor_sync(0xffffffffu, cm1, 1));
        cm1 = fmaxf(cm1, __shfl_xor_sync(0xffffffffu, cm1, 2));
        float mn0 = fmaxf(m0, cm0), mn1 = fmaxf(m1, cm1);
        float sc0 = __expf(m0 - mn0), sc1 = __expf(m1 - mn1);
        m0 = mn0; m1 = mn1;
        float p00 = __expf(s2[0][0] - mn0), p01 = __expf(s2[0][1] - mn0);
        float p02 = __expf(s2[0][2] - mn1), p03 = __expf(s2[0][3] - mn1);
        float p10 = __expf(s2[1][0] - mn0), p11 = __expf(s2[1][1] - mn0);
        float p12 = __expf(s2[1][2] - mn1), p13 = __expf(s2[1][3] - mn1);
        float cs0 = p00 + p01 + p10 + p11;
        float cs1 = p02 + p03 + p12 + p13;
        cs0 += __shfl_xor_sync(0xffffffffu, cs0, 1);
        cs0 += __shfl_xor_sync(0xffffffffu, cs0, 2);
        cs1 += __shfl_xor_sync(0xffffffffu, cs1, 1);
        cs1 += __shfl_xor_sync(0xffffffffu, cs1, 2);
        sum0 = sum0 * sc0 + cs0;
        sum1 = sum1 * sc1 + cs1;
        #pragma unroll
        for (int ht = 0; ht < 8; ht++) {
            oacc[ht][0] *= sc0; oacc[ht][1] *= sc0;
            oacc[ht][2] *= sc1; oacc[ht][3] *= sc1;
        }
        // ---- P fragments (A of k16: 16 s values) ----
        uint32_t Ph[4], Pl[4];
        splith(p00, p01, Ph[0], Pl[0]);
        splith(p02, p03, Ph[1], Pl[1]);
        splith(p10, p11, Ph[2], Pl[2]);
        splith(p12, p13, Ph[3], Pl[3]);
        // ---- PV ----
        #pragma unroll
        for (int hp = 0; hp < 4; hp++) {
            uint32_t VH[4], VL[4];
            LDM4T(VH, sb + TVH * 4 + v_lane + jj * 2304 + hp * 32);
            LDM4T(VL, sb + TVL * 4 + v_lane + jj * 2304 + hp * 32);
            mma_f16(oacc[2*hp],   Ph, VH[0], VH[1]);
            mma_f16(oacc[2*hp+1], Ph, VH[2], VH[3]);
            mma_f16(oacc[2*hp],   Ph, VL[0], VL[1]);
            mma_f16(oacc[2*hp+1], Ph, VL[2], VL[3]);
            mma_f16(oacc[2*hp],   Pl, VH[0], VH[1]);
            mma_f16(oacc[2*hp+1], Pl, VH[2], VH[3]);
        }
    }

    // ---- normalize + store ----
    const float inv0 = 1.0f / sum0, inv1 = 1.0f / sum1;
    float* ob = out + (size_t)b * TQ * HD;
    #pragma unroll
    for (int ht = 0; ht < 8; ht++) {
        int c = ht * 8 + 2 * tg;
        *(float2*)(ob + (size_t)r0 * HD + c) =
            make_float2(oacc[ht][0] * inv0, oacc[ht][1] * inv0);
        *(float2*)(ob + (size_t)r1 * HD + c) =
            make_float2(oacc[ht][2] * inv1, oacc[ht][3] * inv1);
    }
}

// ============================================================================
extern "C" void kernel_launch(void* const* d_in, const int* in_sizes, int n_in,
                              void* d_out, int out_size)
{
    (void)in_sizes; (void)n_in; (void)out_size;
    const float* x  = (const float*)d_in[0];
    const float* Wq = (const float*)d_in[1];
    const float* Wk = (const float*)d_in[2];
    const float* Wv = (const float*)d_in[3];
    float* out = (float*)d_out;

    cudaFuncSetAttribute(proj_kernel,
                         cudaFuncAttributeMaxDynamicSharedMemorySize, PJ_SMEM);
    cudaFuncSetAttribute(attn_kernel,
                         cudaFuncAttributeMaxDynamicSharedMemorySize, AT_SMEM);

    wsplit_kernel<<<(192 * 192 + 255) / 256, 256>>>(Wq, Wk, Wv);
    proj_kernel<<<MTOT / 64, 256, PJ_SMEM>>>(x);
    attn_kernel<<<NB, 256, AT_SMEM>>>(out);
}